// round 4
// baseline (speedup 1.0000x reference)
#include <cuda_runtime.h>

// Problem constants: N=16, M=100, LOC_MAX=10000, EMB=128, D=4
#define N_      16
#define M_      100
#define LOC_    10000
#define EMB_    128
#define TL      128     // l-tile per block
#define THREADS 256
#define MC      10      // m-chunk
#define NC      10      // M_/MC
#define LPT     5       // (MC*TL)/THREADS float4 loads per thread per chunk

// ---- packed f32x2 helpers ----
typedef unsigned long long ull;
__device__ __forceinline__ ull pack2(float lo, float hi) {
    ull r; asm("mov.b64 %0, {%1, %2};" : "=l"(r) : "f"(lo), "f"(hi)); return r;
}
__device__ __forceinline__ void unpack2(ull v, float& lo, float& hi) {
    asm("mov.b64 {%0, %1}, %2;" : "=f"(lo), "=f"(hi) : "l"(v));
}
__device__ __forceinline__ ull fma2(ull a, ull b, ull c) {
    ull d; asm("fma.rn.f32x2 %0, %1, %2, %3;" : "=l"(d) : "l"(a), "l"(b), "l"(c));
    return d;
}

// dynamic smem layout (floats):
//   q_s[M_*EMB_]  = 12800  (q[n,m,:] * w[m])
//   s_s[MC*TL]    =  1280  (sum_d delta, current m-chunk, layout [m_local][l])
//   red[8*TL]     =  1024  (epilogue cross-warp reduction)
#define SMEM_Q    0
#define SMEM_S    (M_ * EMB_)
#define SMEM_RED  (M_ * EMB_ + MC * TL)
#define SMEM_FLOATS (M_ * EMB_ + MC * TL + 8 * TL)

extern __shared__ float smem[];

__global__ __launch_bounds__(THREADS, 2)
void attn_tiled_kernel(const float*  __restrict__ self_attn,   // (N, M, EMB)
                       const float4* __restrict__ delta4,      // (N, M, LOC, 4)
                       const float*  __restrict__ emb_table,   // (LOC+1, EMB)
                       const float*  __restrict__ value_w,     // (M,)
                       float*        __restrict__ out)         // (N, LOC)
{
    const int tid = threadIdx.x;
    const int n   = blockIdx.y;
    const int l0  = blockIdx.x * TL;

    float* q_s = smem + SMEM_Q;
    float* s_s = smem + SMEM_S;
    float* red = smem + SMEM_RED;

    // ---- stage q[n]*w into smem (vectorized) ----
    {
        const float4* qg4 = (const float4*)(self_attn + (size_t)n * (M_ * EMB_));
        float4*       qs4 = (float4*)q_s;
        for (int idx = tid; idx < (M_ * EMB_) / 4; idx += THREADS) {
            float w  = value_w[idx >> 5];
            float4 v = qg4[idx];
            v.x *= w; v.y *= w; v.z *= w; v.w *= w;
            qs4[idx] = v;
        }
    }

    // ---- clamped l for this thread's staging loads (reads always valid) ----
    const float4* dbase = delta4 + (size_t)n * (M_ * LOC_);
    int ml_[LPT];
    int lgc[LPT];
#pragma unroll
    for (int i = 0; i < LPT; ++i) {
        int idx = tid + i * THREADS;
        ml_[i]  = idx >> 7;               // m_local
        int lg  = l0 + (idx & (TL - 1));
        lgc[i]  = lg < LOC_ ? lg : LOC_ - 1;
    }

    // ---- prefetch delta chunk 0 ----
    float4 pre[LPT];
#pragma unroll
    for (int i = 0; i < LPT; ++i)
        pre[i] = dbase[(size_t)ml_[i] * LOC_ + lgc[i]];

    // ---- thread mapping: 4 contiguous l's x 16 embs ----
    const int lt = tid & 31;        // lane: l = 4*lt + j, j=0..3
    const int et = tid >> 5;        // warp: embs [et*16, et*16+16)
    ull h[4][8];
#pragma unroll
    for (int j = 0; j < 4; ++j)
#pragma unroll
        for (int k = 0; k < 8; ++k) h[j][k] = 0ULL;

    const ulonglong2* q2 = (const ulonglong2*)q_s + et * 4;   // +m*32 per row
    const float4*     s4 = (const float4*)s_s + lt;           // +mm*32 per m

    // ---- main pipeline over m-chunks ----
    for (int c = 0; c < NC; ++c) {
        float sv[LPT];
#pragma unroll
        for (int i = 0; i < LPT; ++i)
            sv[i] = (pre[i].x + pre[i].y) + (pre[i].z + pre[i].w);

        __syncthreads();            // previous chunk's compute done
#pragma unroll
        for (int i = 0; i < LPT; ++i)
            s_s[tid + i * THREADS] = sv[i];     // [m_local][l], TL=128 = row

        if (c + 1 < NC) {           // overlap next chunk's DRAM latency
            const float4* dch = dbase + (size_t)(c + 1) * MC * LOC_;
#pragma unroll
            for (int i = 0; i < LPT; ++i)
                pre[i] = dch[(size_t)ml_[i] * LOC_ + lgc[i]];
        }
        __syncthreads();            // s_s visible

        const ulonglong2* qc = q2 + (size_t)(c * MC) * 32;

        // software-pipelined compute over the chunk
        float4 sc = s4[0];
#pragma unroll
        for (int mm = 0; mm < MC; ++mm) {
            float4 sn;
            if (mm + 1 < MC) sn = s4[(mm + 1) * 32];
            ull sp0 = pack2(sc.x, sc.x), sp1 = pack2(sc.y, sc.y);
            ull sp2 = pack2(sc.z, sc.z), sp3 = pack2(sc.w, sc.w);

            const ulonglong2* qr = qc + mm * 32;
#pragma unroll
            for (int k = 0; k < 4; ++k) {
                ulonglong2 v = qr[k];           // warp-broadcast LDS.128
                h[0][2*k]   = fma2(sp0, v.x, h[0][2*k]);
                h[0][2*k+1] = fma2(sp0, v.y, h[0][2*k+1]);
                h[1][2*k]   = fma2(sp1, v.x, h[1][2*k]);
                h[1][2*k+1] = fma2(sp1, v.y, h[1][2*k+1]);
                h[2][2*k]   = fma2(sp2, v.x, h[2][2*k]);
                h[2][2*k+1] = fma2(sp2, v.y, h[2][2*k+1]);
                h[3][2*k]   = fma2(sp3, v.x, h[3][2*k]);
                h[3][2*k+1] = fma2(sp3, v.y, h[3][2*k+1]);
            }
            sc = sn;
        }
    }

    // ---- epilogue: partial dot with emb row, cross-warp reduce in smem ----
#pragma unroll
    for (int j = 0; j < 4; ++j) {
        int l  = 4 * lt + j;
        int lg = l0 + l;
        int lr = lg < LOC_ ? lg : LOC_ - 1;     // clamped read
        const float4* e4 =
            (const float4*)(emb_table + (size_t)(lr + 1) * EMB_) + et * 4;
        float part = 0.f;
#pragma unroll
        for (int k = 0; k < 4; ++k) {
            float4 ev = e4[k];
            float a, b;
            unpack2(h[j][2*k], a, b);
            part = fmaf(ev.x, a, part);
            part = fmaf(ev.y, b, part);
            unpack2(h[j][2*k+1], a, b);
            part = fmaf(ev.z, a, part);
            part = fmaf(ev.w, b, part);
        }
        red[et * TL + l] = part;
    }
    __syncthreads();

    if (tid < TL) {
        int lg = l0 + tid;
        if (lg < LOC_) {
            float r = 0.f;
#pragma unroll
            for (int e = 0; e < 8; ++e) r += red[e * TL + tid];
            out[(size_t)n * LOC_ + lg] = r;
        }
    }
}

extern "C" void kernel_launch(void* const* d_in, const int* in_sizes, int n_in,
                              void* d_out, int out_size)
{
    // metadata order: self_attn, self_delta, traj_len(unused), emb_table, value_w
    const float*  self_attn = (const float*) d_in[0];
    const float4* delta4    = (const float4*)d_in[1];
    const float*  emb_table = (const float*) d_in[3];
    const float*  value_w   = (const float*) d_in[4];
    float* out = (float*)d_out;

    const int smem_bytes = SMEM_FLOATS * (int)sizeof(float);
    cudaFuncSetAttribute(attn_tiled_kernel,
                         cudaFuncAttributeMaxDynamicSharedMemorySize, smem_bytes);

    dim3 grid((LOC_ + TL - 1) / TL, N_);
    attn_tiled_kernel<<<grid, THREADS, smem_bytes>>>(self_attn, delta4,
                                                     emb_table, value_w, out);
}

// round 5
// speedup vs baseline: 1.0038x; 1.0038x over previous
#include <cuda_runtime.h>

// Problem constants: N=16, M=100, LOC_MAX=10000, EMB=128, D=4
#define N_      16
#define M_      100
#define LOC_    10000
#define EMB_    128
#define TL      128     // l-tile per block
#define THREADS 256
#define MC      10      // m-chunk
#define NC      10      // M_/MC
#define LPT     5       // (MC*TL)/THREADS float4 loads per thread per chunk

// ---- packed f32x2 helpers ----
typedef unsigned long long ull;
__device__ __forceinline__ ull pack2(float lo, float hi) {
    ull r; asm("mov.b64 %0, {%1, %2};" : "=l"(r) : "f"(lo), "f"(hi)); return r;
}
__device__ __forceinline__ void unpack2(ull v, float& lo, float& hi) {
    asm("mov.b64 {%0, %1}, %2;" : "=f"(lo), "=f"(hi) : "l"(v));
}
__device__ __forceinline__ ull fma2(ull a, ull b, ull c) {
    ull d; asm("fma.rn.f32x2 %0, %1, %2, %3;" : "=l"(d) : "l"(a), "l"(b), "l"(c));
    return d;
}

// dynamic smem layout (floats):
//   q_s[M_*EMB_]  = 12800  (q[n,m,:] * w[m])
//   s_s[MC*TL]    =  1280  (sum_d delta, current m-chunk, layout [m_local][l])
//   red[8*TL]     =  1024  (epilogue cross-warp reduction)
#define SMEM_Q    0
#define SMEM_S    (M_ * EMB_)
#define SMEM_RED  (M_ * EMB_ + MC * TL)
#define SMEM_FLOATS (M_ * EMB_ + MC * TL + 8 * TL)

extern __shared__ float smem[];

__global__ __launch_bounds__(THREADS, 2)
void attn_tiled_kernel(const float*  __restrict__ self_attn,   // (N, M, EMB)
                       const float4* __restrict__ delta4,      // (N, M, LOC, 4)
                       const float*  __restrict__ emb_table,   // (LOC+1, EMB)
                       const float*  __restrict__ value_w,     // (M,)
                       float*        __restrict__ out)         // (N, LOC)
{
    const int tid = threadIdx.x;
    const int n   = blockIdx.y;
    const int l0  = blockIdx.x * TL;

    float* q_s = smem + SMEM_Q;
    float* s_s = smem + SMEM_S;
    float* red = smem + SMEM_RED;

    // ---- stage q[n]*w into smem (vectorized) ----
    {
        const float4* qg4 = (const float4*)(self_attn + (size_t)n * (M_ * EMB_));
        float4*       qs4 = (float4*)q_s;
        for (int idx = tid; idx < (M_ * EMB_) / 4; idx += THREADS) {
            float w  = value_w[idx >> 5];
            float4 v = qg4[idx];
            v.x *= w; v.y *= w; v.z *= w; v.w *= w;
            qs4[idx] = v;
        }
    }

    // ---- clamped l for this thread's staging loads (reads always valid) ----
    const float4* dbase = delta4 + (size_t)n * (M_ * LOC_);
    int ml_[LPT];
    int lgc[LPT];
#pragma unroll
    for (int i = 0; i < LPT; ++i) {
        int idx = tid + i * THREADS;
        ml_[i]  = idx >> 7;               // m_local
        int lg  = l0 + (idx & (TL - 1));
        lgc[i]  = lg < LOC_ ? lg : LOC_ - 1;
    }

    // ---- prefetch delta chunk 0 ----
    float4 pre[LPT];
#pragma unroll
    for (int i = 0; i < LPT; ++i)
        pre[i] = dbase[(size_t)ml_[i] * LOC_ + lgc[i]];

    // ---- thread mapping: 4 contiguous l's x 16 embs ----
    const int lt = tid & 31;        // lane: l = 4*lt + j, j=0..3
    const int et = tid >> 5;        // warp: embs [et*16, et*16+16)
    ull h[4][8];
#pragma unroll
    for (int j = 0; j < 4; ++j)
#pragma unroll
        for (int k = 0; k < 8; ++k) h[j][k] = 0ULL;

    const ulonglong2* q2 = (const ulonglong2*)q_s + et * 4;   // +m*32 per row
    const float4*     s4 = (const float4*)s_s + lt;           // +mm*32 per m

    // ---- main pipeline over m-chunks ----
    for (int c = 0; c < NC; ++c) {
        float sv[LPT];
#pragma unroll
        for (int i = 0; i < LPT; ++i)
            sv[i] = (pre[i].x + pre[i].y) + (pre[i].z + pre[i].w);

        __syncthreads();            // previous chunk's compute done
#pragma unroll
        for (int i = 0; i < LPT; ++i)
            s_s[tid + i * THREADS] = sv[i];     // [m_local][l], TL=128 = row

        if (c + 1 < NC) {           // overlap next chunk's DRAM latency
            const float4* dch = dbase + (size_t)(c + 1) * MC * LOC_;
#pragma unroll
            for (int i = 0; i < LPT; ++i)
                pre[i] = dch[(size_t)ml_[i] * LOC_ + lgc[i]];
        }
        __syncthreads();            // s_s visible

        const ulonglong2* qc = q2 + (size_t)(c * MC) * 32;

        // software-pipelined compute over the chunk
        float4 sc = s4[0];
#pragma unroll
        for (int mm = 0; mm < MC; ++mm) {
            float4 sn;
            if (mm + 1 < MC) sn = s4[(mm + 1) * 32];
            ull sp0 = pack2(sc.x, sc.x), sp1 = pack2(sc.y, sc.y);
            ull sp2 = pack2(sc.z, sc.z), sp3 = pack2(sc.w, sc.w);

            const ulonglong2* qr = qc + mm * 32;
#pragma unroll
            for (int k = 0; k < 4; ++k) {
                ulonglong2 v = qr[k];           // warp-broadcast LDS.128
                h[0][2*k]   = fma2(sp0, v.x, h[0][2*k]);
                h[0][2*k+1] = fma2(sp0, v.y, h[0][2*k+1]);
                h[1][2*k]   = fma2(sp1, v.x, h[1][2*k]);
                h[1][2*k+1] = fma2(sp1, v.y, h[1][2*k+1]);
                h[2][2*k]   = fma2(sp2, v.x, h[2][2*k]);
                h[2][2*k+1] = fma2(sp2, v.y, h[2][2*k+1]);
                h[3][2*k]   = fma2(sp3, v.x, h[3][2*k]);
                h[3][2*k+1] = fma2(sp3, v.y, h[3][2*k+1]);
            }
            sc = sn;
        }
    }

    // ---- epilogue: partial dot with emb row, cross-warp reduce in smem ----
#pragma unroll
    for (int j = 0; j < 4; ++j) {
        int l  = 4 * lt + j;
        int lg = l0 + l;
        int lr = lg < LOC_ ? lg : LOC_ - 1;     // clamped read
        const float4* e4 =
            (const float4*)(emb_table + (size_t)(lr + 1) * EMB_) + et * 4;
        float part = 0.f;
#pragma unroll
        for (int k = 0; k < 4; ++k) {
            float4 ev = e4[k];
            float a, b;
            unpack2(h[j][2*k], a, b);
            part = fmaf(ev.x, a, part);
            part = fmaf(ev.y, b, part);
            unpack2(h[j][2*k+1], a, b);
            part = fmaf(ev.z, a, part);
            part = fmaf(ev.w, b, part);
        }
        red[et * TL + l] = part;
    }
    __syncthreads();

    if (tid < TL) {
        int lg = l0 + tid;
        if (lg < LOC_) {
            float r = 0.f;
#pragma unroll
            for (int e = 0; e < 8; ++e) r += red[e * TL + tid];
            out[(size_t)n * LOC_ + lg] = r;
        }
    }
}

extern "C" void kernel_launch(void* const* d_in, const int* in_sizes, int n_in,
                              void* d_out, int out_size)
{
    // metadata order: self_attn, self_delta, traj_len(unused), emb_table, value_w
    const float*  self_attn = (const float*) d_in[0];
    const float4* delta4    = (const float4*)d_in[1];
    const float*  emb_table = (const float*) d_in[3];
    const float*  value_w   = (const float*) d_in[4];
    float* out = (float*)d_out;

    const int smem_bytes = SMEM_FLOATS * (int)sizeof(float);
    cudaFuncSetAttribute(attn_tiled_kernel,
                         cudaFuncAttributeMaxDynamicSharedMemorySize, smem_bytes);

    dim3 grid((LOC_ + TL - 1) / TL, N_);
    attn_tiled_kernel<<<grid, THREADS, smem_bytes>>>(self_attn, delta4,
                                                     emb_table, value_w, out);
}

// round 6
// speedup vs baseline: 1.0130x; 1.0092x over previous
#include <cuda_runtime.h>

// Problem constants: N=16, M=100, LOC_MAX=10000, EMB=128, D=4
#define N_      16
#define M_      100
#define LOC_    10000
#define EMB_    128
#define TL      128     // l-tile per block
#define THREADS 256
#define MC      10      // m-chunk
#define NC      10      // M_/MC
#define LPT     5       // (MC*TL)/THREADS float4 loads per thread per chunk

// ---- packed f32x2 helpers ----
typedef unsigned long long ull;
__device__ __forceinline__ ull pack2(float lo, float hi) {
    ull r; asm("mov.b64 %0, {%1, %2};" : "=l"(r) : "f"(lo), "f"(hi)); return r;
}
__device__ __forceinline__ void unpack2(ull v, float& lo, float& hi) {
    asm("mov.b64 {%0, %1}, %2;" : "=f"(lo), "=f"(hi) : "l"(v));
}
__device__ __forceinline__ ull fma2(ull a, ull b, ull c) {
    ull d; asm("fma.rn.f32x2 %0, %1, %2, %3;" : "=l"(d) : "l"(a), "l"(b), "l"(c));
    return d;
}

// dynamic smem layout (floats):
//   q_s[M_*EMB_]  = 12800  (q[n,m,:] * w[m])
//   s_s[MC*TL]    =  1280  (sum_d delta, current m-chunk, layout [m_local][l])
//   red[8*TL]     =  1024  (epilogue cross-warp reduction)
#define SMEM_Q    0
#define SMEM_S    (M_ * EMB_)
#define SMEM_RED  (M_ * EMB_ + MC * TL)
#define SMEM_FLOATS (M_ * EMB_ + MC * TL + 8 * TL)

extern __shared__ float smem[];

__global__ __launch_bounds__(THREADS, 2)
void attn_tiled_kernel(const float*  __restrict__ self_attn,   // (N, M, EMB)
                       const float4* __restrict__ delta4,      // (N, M, LOC, 4)
                       const float*  __restrict__ emb_table,   // (LOC+1, EMB)
                       const float*  __restrict__ value_w,     // (M,)
                       float*        __restrict__ out)         // (N, LOC)
{
    const int tid = threadIdx.x;
    const int n   = blockIdx.y;
    const int l0  = blockIdx.x * TL;

    float* q_s = smem + SMEM_Q;
    float* s_s = smem + SMEM_S;
    float* red = smem + SMEM_RED;

    // ---- stage q[n]*w into smem (vectorized) ----
    {
        const float4* qg4 = (const float4*)(self_attn + (size_t)n * (M_ * EMB_));
        float4*       qs4 = (float4*)q_s;
        for (int idx = tid; idx < (M_ * EMB_) / 4; idx += THREADS) {
            float w  = value_w[idx >> 5];
            float4 v = qg4[idx];
            v.x *= w; v.y *= w; v.z *= w; v.w *= w;
            qs4[idx] = v;
        }
    }

    // ---- clamped l for this thread's staging loads (reads always valid) ----
    const float4* dbase = delta4 + (size_t)n * (M_ * LOC_);
    int ml_[LPT];
    int lgc[LPT];
#pragma unroll
    for (int i = 0; i < LPT; ++i) {
        int idx = tid + i * THREADS;
        ml_[i]  = idx >> 7;               // m_local
        int lg  = l0 + (idx & (TL - 1));
        lgc[i]  = lg < LOC_ ? lg : LOC_ - 1;
    }

    // ---- prefetch delta chunk 0 ----
    float4 pre[LPT];
#pragma unroll
    for (int i = 0; i < LPT; ++i)
        pre[i] = dbase[(size_t)ml_[i] * LOC_ + lgc[i]];

    // ---- thread mapping: 4 contiguous l's x 16 embs ----
    const int lt = tid & 31;        // lane: l = 4*lt + j, j=0..3
    const int et = tid >> 5;        // warp: embs [et*16, et*16+16)
    ull h[4][8];
#pragma unroll
    for (int j = 0; j < 4; ++j)
#pragma unroll
        for (int k = 0; k < 8; ++k) h[j][k] = 0ULL;

    const ulonglong2* q2 = (const ulonglong2*)q_s + et * 4;   // +m*32 per row
    const float4*     s4 = (const float4*)s_s + lt;           // +mm*32 per m

    // ---- main pipeline over m-chunks ----
    for (int c = 0; c < NC; ++c) {
        float sv[LPT];
#pragma unroll
        for (int i = 0; i < LPT; ++i)
            sv[i] = (pre[i].x + pre[i].y) + (pre[i].z + pre[i].w);

        __syncthreads();            // previous chunk's compute done
#pragma unroll
        for (int i = 0; i < LPT; ++i)
            s_s[tid + i * THREADS] = sv[i];     // [m_local][l], TL=128 = row

        if (c + 1 < NC) {           // overlap next chunk's DRAM latency
            const float4* dch = dbase + (size_t)(c + 1) * MC * LOC_;
#pragma unroll
            for (int i = 0; i < LPT; ++i)
                pre[i] = dch[(size_t)ml_[i] * LOC_ + lgc[i]];
        }
        __syncthreads();            // s_s visible

        const ulonglong2* qc = q2 + (size_t)(c * MC) * 32;

        // software-pipelined compute over the chunk
        float4 sc = s4[0];
#pragma unroll
        for (int mm = 0; mm < MC; ++mm) {
            float4 sn;
            if (mm + 1 < MC) sn = s4[(mm + 1) * 32];
            ull sp0 = pack2(sc.x, sc.x), sp1 = pack2(sc.y, sc.y);
            ull sp2 = pack2(sc.z, sc.z), sp3 = pack2(sc.w, sc.w);

            const ulonglong2* qr = qc + mm * 32;
#pragma unroll
            for (int k = 0; k < 4; ++k) {
                ulonglong2 v = qr[k];           // warp-broadcast LDS.128
                h[0][2*k]   = fma2(sp0, v.x, h[0][2*k]);
                h[0][2*k+1] = fma2(sp0, v.y, h[0][2*k+1]);
                h[1][2*k]   = fma2(sp1, v.x, h[1][2*k]);
                h[1][2*k+1] = fma2(sp1, v.y, h[1][2*k+1]);
                h[2][2*k]   = fma2(sp2, v.x, h[2][2*k]);
                h[2][2*k+1] = fma2(sp2, v.y, h[2][2*k+1]);
                h[3][2*k]   = fma2(sp3, v.x, h[3][2*k]);
                h[3][2*k+1] = fma2(sp3, v.y, h[3][2*k+1]);
            }
            sc = sn;
        }
    }

    // ---- epilogue: partial dot with emb row, cross-warp reduce in smem ----
#pragma unroll
    for (int j = 0; j < 4; ++j) {
        int l  = 4 * lt + j;
        int lg = l0 + l;
        int lr = lg < LOC_ ? lg : LOC_ - 1;     // clamped read
        const float4* e4 =
            (const float4*)(emb_table + (size_t)(lr + 1) * EMB_) + et * 4;
        float part = 0.f;
#pragma unroll
        for (int k = 0; k < 4; ++k) {
            float4 ev = e4[k];
            float a, b;
            unpack2(h[j][2*k], a, b);
            part = fmaf(ev.x, a, part);
            part = fmaf(ev.y, b, part);
            unpack2(h[j][2*k+1], a, b);
            part = fmaf(ev.z, a, part);
            part = fmaf(ev.w, b, part);
        }
        red[et * TL + l] = part;
    }
    __syncthreads();

    if (tid < TL) {
        int lg = l0 + tid;
        if (lg < LOC_) {
            float r = 0.f;
#pragma unroll
            for (int e = 0; e < 8; ++e) r += red[e * TL + tid];
            out[(size_t)n * LOC_ + lg] = r;
        }
    }
}

extern "C" void kernel_launch(void* const* d_in, const int* in_sizes, int n_in,
                              void* d_out, int out_size)
{
    // metadata order: self_attn, self_delta, traj_len(unused), emb_table, value_w
    const float*  self_attn = (const float*) d_in[0];
    const float4* delta4    = (const float4*)d_in[1];
    const float*  emb_table = (const float*) d_in[3];
    const float*  value_w   = (const float*) d_in[4];
    float* out = (float*)d_out;

    const int smem_bytes = SMEM_FLOATS * (int)sizeof(float);
    cudaFuncSetAttribute(attn_tiled_kernel,
                         cudaFuncAttributeMaxDynamicSharedMemorySize, smem_bytes);

    dim3 grid((LOC_ + TL - 1) / TL, N_);
    attn_tiled_kernel<<<grid, THREADS, smem_bytes>>>(self_attn, delta4,
                                                     emb_table, value_w, out);
}